// round 13
// baseline (speedup 1.0000x reference)
#include <cuda_runtime.h>
#include <cuda_bf16.h>
#include <cstdint>

#define NLEV 4
#define MAXS 792
#define NTHREADS 256

// Packed table: level sizes 36/72/216/792 -> offsets 0/36/108/324, 1116 float2 (8.9KB)
#define T_TOT 1116

// R12: depth-2 register software pipeline. While computing level l, levels l+1
// AND l+2 are in flight. 3 register buffers, no smem staging for streamed data.
__global__ __launch_bounds__(NTHREADS, 2) void heal_encoding_regpipe2(
    const float2* __restrict__ params2,      // [NLEV, MAXS] float2
    const float2* __restrict__ pixel_ll,     // [NLEV, B]
    const float2* __restrict__ neigh_ll,     // [NLEV, 8, B]
    const int*    __restrict__ pixel_idx,    // [NLEV, B]
    const int*    __restrict__ neigh_idx,    // [NLEV, 8, B]
    float*        __restrict__ out,          // [B, 8]  out[b, 4f+l]
    int B)
{
    __shared__ float2 tab[T_TOT];
    __shared__ int    toff_s[NLEV];
    {
        const int tsz[NLEV]  = {36, 72, 216, 792};
        const int toff[NLEV] = {0, 36, 108, 324};
        if (threadIdx.x < NLEV) toff_s[threadIdx.x] = toff[threadIdx.x];
#pragma unroll
        for (int l = 0; l < NLEV; l++)
            for (int i = threadIdx.x; i < tsz[l]; i += NTHREADS)
                tab[toff[l] + i] = params2[l * MAXS + i];
    }
    __syncthreads();

    const int b = blockIdx.x * NTHREADS + threadIdx.x;
    if (b >= B) return;

    // triple-buffered per-level inputs (registers)
    int    nidx[3][8];
    float2 nll [3][8];
    int    p   [3];
    float2 pl  [3];

    // prologue: levels 0 and 1 in flight
#pragma unroll
    for (int l0 = 0; l0 < 2; l0++) {
#pragma unroll
        for (int j = 0; j < 8; j++)
            nidx[l0][j] = __ldcs(neigh_idx + (size_t)(l0 * 8 + j) * B + b);
#pragma unroll
        for (int j = 0; j < 8; j++)
            nll[l0][j]  = __ldcs(neigh_ll  + (size_t)(l0 * 8 + j) * B + b);
        p[l0]  = __ldcs(pixel_idx + (size_t)l0 * B + b);
        pl[l0] = __ldcs(pixel_ll  + (size_t)l0 * B + b);
    }

    float acc0[NLEV], acc1[NLEV];

#pragma unroll
    for (int l = 0; l < NLEV; l++) {
        const int cur = l % 3;

        // issue level l+2's loads (consumed two iterations from now)
        if (l + 2 < NLEV) {
            const int nx = (l + 2) % 3;
#pragma unroll
            for (int j = 0; j < 8; j++)
                nidx[nx][j] = __ldcs(neigh_idx + (size_t)((l + 2) * 8 + j) * B + b);
#pragma unroll
            for (int j = 0; j < 8; j++)
                nll[nx][j]  = __ldcs(neigh_ll  + (size_t)((l + 2) * 8 + j) * B + b);
            p[nx]  = __ldcs(pixel_idx + (size_t)(l + 2) * B + b);
            pl[nx] = __ldcs(pixel_ll  + (size_t)(l + 2) * B + b);
        }

        // compute level l (its loads have had ~2 compute phases to land)
        const int    to = toff_s[l];
        const float2 P  = pl[cur];
        const float2 r  = tab[to + p[cur]];
        float s0 = r.x, s1 = r.y;
#pragma unroll
        for (int j = 0; j < 8; j++) {
            const int    n  = nidx[cur][j];
            const float2 ll = nll[cur][j];
            const float dphi = ll.y - P.y;
            const float dth  = ll.x - P.x;
            float w = rsqrtf(fmaf(dphi, dphi, dth * dth));
            w = (n >= 0) ? w : 0.0f;
            const float2 v = tab[to + (n >= 0 ? n : 0)];
            s0 = fmaf(w, v.x, s0);
            s1 = fmaf(w, v.y, s1);
        }
        acc0[l] = s0;
        acc1[l] = s1;
    }

    // out[b, 4f + l]: 8 contiguous floats -> two float4 stores
    float4* op = reinterpret_cast<float4*>(out + (size_t)b * 8);
    op[0] = make_float4(acc0[0], acc0[1], acc0[2], acc0[3]);
    op[1] = make_float4(acc1[0], acc1[1], acc1[2], acc1[3]);
}

extern "C" void kernel_launch(void* const* d_in, const int* in_sizes, int n_in,
                              void* d_out, int out_size)
{
    // metadata order: params, pixel_latlon, neigh_latlon, pixel_index, neigh_index
    const float2* params2   = (const float2*)d_in[0];
    const float2* pixel_ll  = (const float2*)d_in[1];
    const float2* neigh_ll  = (const float2*)d_in[2];
    const int*    pixel_idx = (const int*)d_in[3];
    const int*    neigh_idx = (const int*)d_in[4];
    float*        out       = (float*)d_out;

    const int B = in_sizes[3] / NLEV;   // pixel_index has NLEV*B elements

    const int grid = (B + NTHREADS - 1) / NTHREADS;
    heal_encoding_regpipe2<<<grid, NTHREADS>>>(
        params2, pixel_ll, neigh_ll, pixel_idx, neigh_idx, out, B);
}

// round 14
// speedup vs baseline: 1.0323x; 1.0323x over previous
#include <cuda_runtime.h>
#include <cuda_bf16.h>
#include <cstdint>

#define NLEV 4
#define MAXS 792
#define NTHREADS 256

// Packed table: level sizes 36/72/216/792 -> offsets 0/36/108/324, 1116 float2 (8.9KB)
#define T_TOT 1116

// R13: R12 depth-1 register pipeline + (a) prologue loads issued BEFORE the
// table-copy/barrier so level-0 latency is covered by the table phase,
// (b) streaming stores (__stcs) for the write-once output.
__global__ __launch_bounds__(NTHREADS, 3) void heal_encoding_regpipe3(
    const float2* __restrict__ params2,      // [NLEV, MAXS] float2
    const float2* __restrict__ pixel_ll,     // [NLEV, B]
    const float2* __restrict__ neigh_ll,     // [NLEV, 8, B]
    const int*    __restrict__ pixel_idx,    // [NLEV, B]
    const int*    __restrict__ neigh_idx,    // [NLEV, 8, B]
    float*        __restrict__ out,          // [B, 8]  out[b, 4f+l]
    int B)
{
    __shared__ float2 tab[T_TOT];
    __shared__ int    toff_s[NLEV];

    const int b = blockIdx.x * NTHREADS + threadIdx.x;
    const bool active = (b < B);
    const int bl = active ? b : 0;           // safe address for inactive threads

    // double-buffered per-level inputs (registers)
    int    nidx[2][8];
    float2 nll [2][8];
    int    p   [2];
    float2 pl  [2];

    // ---- prologue: issue level 0's 18 loads FIRST (covered by table phase) ----
#pragma unroll
    for (int j = 0; j < 8; j++)
        nidx[0][j] = __ldcs(neigh_idx + (size_t)(0 * 8 + j) * B + bl);
#pragma unroll
    for (int j = 0; j < 8; j++)
        nll[0][j]  = __ldcs(neigh_ll  + (size_t)(0 * 8 + j) * B + bl);
    p[0]  = __ldcs(pixel_idx + (size_t)0 * B + bl);
    pl[0] = __ldcs(pixel_ll  + (size_t)0 * B + bl);

    // ---- table copy (gmem->smem) + barrier: covers level-0 load latency ----
    {
        const int tsz[NLEV]  = {36, 72, 216, 792};
        const int toff[NLEV] = {0, 36, 108, 324};
        if (threadIdx.x < NLEV) toff_s[threadIdx.x] = toff[threadIdx.x];
#pragma unroll
        for (int l = 0; l < NLEV; l++)
            for (int i = threadIdx.x; i < tsz[l]; i += NTHREADS)
                tab[toff[l] + i] = params2[l * MAXS + i];
    }
    __syncthreads();

    if (!active) return;

    float acc0[NLEV], acc1[NLEV];

#pragma unroll
    for (int l = 0; l < NLEV; l++) {
        const int cur = l & 1;
        const int nxt = cur ^ 1;

        // issue next level's loads first (consumed next iteration)
        if (l + 1 < NLEV) {
#pragma unroll
            for (int j = 0; j < 8; j++)
                nidx[nxt][j] = __ldcs(neigh_idx + (size_t)((l + 1) * 8 + j) * B + b);
#pragma unroll
            for (int j = 0; j < 8; j++)
                nll[nxt][j]  = __ldcs(neigh_ll  + (size_t)((l + 1) * 8 + j) * B + b);
            p[nxt]  = __ldcs(pixel_idx + (size_t)(l + 1) * B + b);
            pl[nxt] = __ldcs(pixel_ll  + (size_t)(l + 1) * B + b);
        }

        // compute level l from buffer cur
        const int    to = toff_s[l];
        const float2 P  = pl[cur];
        const float2 r  = tab[to + p[cur]];
        float s0 = r.x, s1 = r.y;
#pragma unroll
        for (int j = 0; j < 8; j++) {
            const int    n  = nidx[cur][j];
            const float2 ll = nll[cur][j];
            const float dphi = ll.y - P.y;
            const float dth  = ll.x - P.x;
            float w = rsqrtf(fmaf(dphi, dphi, dth * dth));
            w = (n >= 0) ? w : 0.0f;
            const float2 v = tab[to + (n >= 0 ? n : 0)];
            s0 = fmaf(w, v.x, s0);
            s1 = fmaf(w, v.y, s1);
        }
        acc0[l] = s0;
        acc1[l] = s1;
    }

    // out[b, 4f + l]: 8 contiguous floats -> two streaming float4 stores
    float4* op = reinterpret_cast<float4*>(out + (size_t)b * 8);
    __stcs(op,     make_float4(acc0[0], acc0[1], acc0[2], acc0[3]));
    __stcs(op + 1, make_float4(acc1[0], acc1[1], acc1[2], acc1[3]));
}

extern "C" void kernel_launch(void* const* d_in, const int* in_sizes, int n_in,
                              void* d_out, int out_size)
{
    // metadata order: params, pixel_latlon, neigh_latlon, pixel_index, neigh_index
    const float2* params2   = (const float2*)d_in[0];
    const float2* pixel_ll  = (const float2*)d_in[1];
    const float2* neigh_ll  = (const float2*)d_in[2];
    const int*    pixel_idx = (const int*)d_in[3];
    const int*    neigh_idx = (const int*)d_in[4];
    float*        out       = (float*)d_out;

    const int B = in_sizes[3] / NLEV;   // pixel_index has NLEV*B elements

    const int grid = (B + NTHREADS - 1) / NTHREADS;
    heal_encoding_regpipe3<<<grid, NTHREADS>>>(
        params2, pixel_ll, neigh_ll, pixel_idx, neigh_idx, out, B);
}